// round 14
// baseline (speedup 1.0000x reference)
#include <cuda_runtime.h>
#include <cuda_bf16.h>
#include <cuda_fp16.h>
#include <cstdint>

#define NN 50000
#define EE 500000
#define DD 256
#define HH 4
#define MAXDEG 96

// ------------------- device scratch (no allocations allowed) -------------------
// 128-col sections in NATURAL order: col = h*32 + k. float4 at lane*4 holds
// (h = lane>>3, k = (lane&7)*4 .. +3).
__device__ float g_WcatT[384 * 256];    // [n=384][k=256], tf32-rounded. rows: 0-127 v | 128-255 A_src | 256-383 A_tgt
__device__ float g_WfT[256 * 128];      // [n=256][k=128], tf32-rounded
__device__ float g_big[NN * 384];       // [N, 384] fp32
__device__ float g_Apos[129 * 128];     // [pos][h*32+k] fp32
__device__ float g_Bdr[64 * 4];         // [deprel][h]
__device__ float g_Bda[8 * 4];          // [deparc][h]
__device__ float g_agg[NN * 128];       // [n][h*32+dv], tf32-rounded (GEMM2 A operand)
__device__ int   g_cnt[NN];
__device__ int2  g_slot2[NN * MAXDEG];  // packed: w0 = src|relpos<<16|deprel<<23|deparc<<29, w1 = e
__device__ uint2 g_exh[(size_t)EE * 32]; // per-edge exps, 4 x fp16 per lane (128 MB)

// ------------------- helpers -------------------
__device__ __forceinline__ unsigned f2tf(float x) {
    unsigned r;
    asm("cvt.rna.tf32.f32 %0, %1;" : "=r"(r) : "f"(x));
    return r;
}
__device__ __forceinline__ float f2tff(float x) { return __uint_as_float(f2tf(x)); }

__device__ __forceinline__ unsigned pack_h2(float lo, float hi) {
    unsigned r;
    asm("cvt.rn.f16x2.f32 %0, %1, %2;" : "=r"(r) : "f"(hi), "f"(lo));
    return r;
}

__device__ __forceinline__ void cp_async16(void* smem, const void* gmem, bool pred) {
    unsigned sa = (unsigned)__cvta_generic_to_shared(smem);
    int sz = pred ? 16 : 0;
    asm volatile("cp.async.cg.shared.global [%0], [%1], 16, %2;" :: "r"(sa), "l"(gmem), "r"(sz));
}
__device__ __forceinline__ void cp_commit() { asm volatile("cp.async.commit_group;"); }
__device__ __forceinline__ void cp_wait0() { asm volatile("cp.async.wait_group 0;" ::: "memory"); }

__device__ __forceinline__ void mma_tf32(float* c, const unsigned* a, const unsigned* b) {
    asm volatile(
        "mma.sync.aligned.m16n8k8.row.col.f32.tf32.tf32.f32 "
        "{%0,%1,%2,%3}, {%4,%5,%6,%7}, {%8,%9}, {%0,%1,%2,%3};"
        : "+f"(c[0]), "+f"(c[1]), "+f"(c[2]), "+f"(c[3])
        : "r"(a[0]), "r"(a[1]), "r"(a[2]), "r"(a[3]), "r"(b[0]), "r"(b[1]));
}

// ------------------- merged prep kernel (zero cnt + weights + tables) -------------------
__global__ void prep_all_kernel(const float* __restrict__ Wkq,
                                const float* __restrict__ Wv,
                                const float* __restrict__ att_w,
                                const float* __restrict__ Wf,
                                const float* __restrict__ E_pos,
                                const float* __restrict__ E_deprel,
                                const float* __restrict__ E_deparc,
                                const float* __restrict__ edge_w) {
    int t = blockIdx.x * blockDim.x + threadIdx.x;
    if (t < NN) g_cnt[t] = 0;

    if (t < 384 * 256) {
        int c = t >> 8, d = t & 255;
        int sec = c >> 7;
        int m = c & 127;               // m = h*32 + k (natural)
        int h = m >> 5, k = m & 31;
        float o;
        if (sec == 0) {
            o = Wv[d * 128 + m];
        } else {
            int joff = (sec == 2) ? 32 : 0;
            float s = 0.f;
            #pragma unroll
            for (int j = 0; j < 32; j++)
                s += Wkq[d * 128 + h * 32 + j] * att_w[h * 3072 + (joff + j) * 32 + k];
            o = s;
        }
        g_WcatT[c * 256 + d] = f2tff(o);
        return;
    }
    int u = t - 384 * 256;
    if (u < 256 * 128) {
        int c = u & 127, n = u >> 7;
        g_WfT[n * 128 + c] = f2tff(Wf[c * 256 + n]);
        return;
    }
    u -= 256 * 128;
    if (u < 129 * 128) {
        int p = u >> 7, m = u & 127;
        int h = m >> 5, k = m & 31;
        float s = 0.f;
        #pragma unroll
        for (int j = 0; j < 32; j++)
            s += E_pos[p * 32 + j] * att_w[h * 3072 + (64 + j) * 32 + k];
        g_Apos[u] = s;
        return;
    }
    u -= 129 * 128;
    if (u < 256) {
        int r = u / 4, h = u % 4;
        float s = 0.f;
        #pragma unroll
        for (int j = 0; j < 32; j++)
            s += E_deprel[r * 32 + j] * edge_w[h * 96 + j];
        g_Bdr[u] = s;
        return;
    }
    u -= 256;
    if (u < 32) {
        int a = u / 4, h = u % 4;
        float s = 0.f;
        #pragma unroll
        for (int j = 0; j < 32; j++)
            s += E_deparc[a * 32 + j] * edge_w[h * 96 + 32 + j];
        g_Bda[u] = s;
    }
}

// ------------------- scatter: pack all per-edge scalars into the slot record -------------------
__global__ void scatter_kernel(const int* __restrict__ edge_index,
                               const int* __restrict__ relpos,
                               const int* __restrict__ deprel,
                               const int* __restrict__ deparc) {
    int e = blockIdx.x * blockDim.x + threadIdx.x;
    if (e >= EE) return;
    int t  = edge_index[EE + e];
    int s  = edge_index[e];
    int rp = relpos[e];          // 0..64 -> 7 bits
    int dr = deprel[e];          // 0..63 -> 6 bits
    int da = deparc[e];          // 0..7  -> 3 bits
    int w0 = s | (rp << 16) | (dr << 23) | (da << 29);
    int r = atomicAdd(&g_cnt[t], 1);
    if (r < MAXDEG) g_slot2[t * MAXDEG + r] = make_int2(w0, e);
}

// ------------------- tf32 mma.sync GEMM, cp.async double-buffered (round-3 proven) -------------------
template<bool ACVT>
__device__ __forceinline__ void gemm_body(int M, int K,
                                          const float* __restrict__ A, int lda,
                                          const float* __restrict__ BT, int ldbt,
                                          float* __restrict__ C, int ldc,
                                          const float* __restrict__ bias,
                                          float (*As)[128 * 32], float (*Bs)[64 * 32]) {
    int m0 = blockIdx.y * 128;
    int n0 = blockIdx.x * 64;
    int tid = threadIdx.x;
    int wid = tid >> 5, lane = tid & 31;
    int wm = (wid & 3) * 32;
    int wn = (wid >> 2) * 32;
    int r = lane >> 2, cq = lane & 3;

    float acc[2][4][4];
    #pragma unroll
    for (int i = 0; i < 2; i++)
        #pragma unroll
        for (int j = 0; j < 4; j++)
            #pragma unroll
            for (int q = 0; q < 4; q++) acc[i][j][q] = 0.f;

    auto stage = [&](int buf, int k0) {
        #pragma unroll
        for (int l = 0; l < 4; l++) {
            int idx = tid + l * 256;
            int row = idx >> 3, c = idx & 7;
            float* dst = As[buf] + row * 32 + ((c ^ (row & 7)) << 2);
            cp_async16(dst, A + (size_t)(m0 + row) * lda + k0 + c * 4, m0 + row < M);
        }
        #pragma unroll
        for (int l = 0; l < 2; l++) {
            int idx = tid + l * 256;
            int row = idx >> 3, c = idx & 7;
            float* dst = Bs[buf] + row * 32 + ((c ^ (row & 7)) << 2);
            cp_async16(dst, BT + (size_t)(n0 + row) * ldbt + k0 + c * 4, true);
        }
    };

    int T = K >> 5;
    stage(0, 0);
    cp_commit();

    for (int t = 0; t < T; t++) {
        cp_wait0();
        __syncthreads();
        if (t + 1 < T) { stage((t + 1) & 1, (t + 1) * 32); cp_commit(); }

        const float* Ab = As[t & 1];
        const float* Bb = Bs[t & 1];
        #pragma unroll
        for (int kf = 0; kf < 4; kf++) {
            int o0 = (((2 * kf) ^ r) << 2) + cq;
            int o1 = (((2 * kf + 1) ^ r) << 2) + cq;
            unsigned afr[2][4], bfr[4][2];
            #pragma unroll
            for (int mf = 0; mf < 2; mf++) {
                const float* b0 = Ab + (wm + mf * 16 + r) * 32;
                const float* b8 = b0 + 8 * 32;
                if (ACVT) {
                    afr[mf][0] = f2tf(b0[o0]); afr[mf][1] = f2tf(b8[o0]);
                    afr[mf][2] = f2tf(b0[o1]); afr[mf][3] = f2tf(b8[o1]);
                } else {
                    afr[mf][0] = __float_as_uint(b0[o0]); afr[mf][1] = __float_as_uint(b8[o0]);
                    afr[mf][2] = __float_as_uint(b0[o1]); afr[mf][3] = __float_as_uint(b8[o1]);
                }
            }
            #pragma unroll
            for (int nf = 0; nf < 4; nf++) {
                const float* bb = Bb + (wn + nf * 8 + r) * 32;
                bfr[nf][0] = __float_as_uint(bb[o0]);
                bfr[nf][1] = __float_as_uint(bb[o1]);
            }
            #pragma unroll
            for (int mf = 0; mf < 2; mf++)
                #pragma unroll
                for (int nf = 0; nf < 4; nf++)
                    mma_tf32(acc[mf][nf], afr[mf], bfr[nf]);
        }
        __syncthreads();
    }

    #pragma unroll
    for (int mf = 0; mf < 2; mf++) {
        #pragma unroll
        for (int nf = 0; nf < 4; nf++) {
            int col = n0 + wn + nf * 8 + cq * 2;
            float b0 = 0.f, b1 = 0.f;
            if (bias) { b0 = bias[col]; b1 = bias[col + 1]; }
            int row0 = m0 + wm + mf * 16 + r;
            if (row0 < M)
                *(float2*)(C + (size_t)row0 * ldc + col) =
                    make_float2(acc[mf][nf][0] + b0, acc[mf][nf][1] + b1);
            int row1 = row0 + 8;
            if (row1 < M)
                *(float2*)(C + (size_t)row1 * ldc + col) =
                    make_float2(acc[mf][nf][2] + b0, acc[mf][nf][3] + b1);
        }
    }
}

__global__ void gemm1_kernel(const float* __restrict__ inp) {
    __shared__ float As[2][128 * 32];
    __shared__ float Bs[2][64 * 32];
    gemm_body<true>(NN, 256, inp, 256, g_WcatT, 256, g_big, 384, nullptr, As, Bs);
}

__global__ void gemm2_kernel(const float* __restrict__ bias, float* __restrict__ out) {
    __shared__ float As[2][128 * 32];
    __shared__ float Bs[2][64 * 32];
    gemm_body<false>(NN, 128, g_agg, 128, g_WfT, 128, out, 256, bias, As, Bs);
}

// ------------------- edge/attention kernel: one warp per target node -------------------
// Natural [h*32+k] layout; packed slot records. Pass 1 computes denominators AND
// stores the per-edge exps (4 x fp16 per lane) to g_exh; pass 2 just reloads them
// -> no score recompute, no as/ap gathers, half the MUFU work.
__global__ void edge_kernel(const float* __restrict__ edge_w,
                            float* __restrict__ attn) {
    int warp = (blockIdx.x * blockDim.x + threadIdx.x) >> 5;
    int lane = threadIdx.x & 31;
    if (warp >= NN) return;
    int n = warp;
    int h = lane >> 3;
    int kb = (lane & 7) * 4;

    float4 at4 = *(const float4*)(g_big + (size_t)n * 384 + 256 + lane * 4);
    float ew0 = edge_w[h * 96 + 64 + kb + 0];
    float ew1 = edge_w[h * 96 + 64 + kb + 1];
    float ew2 = edge_w[h * 96 + 64 + kb + 2];
    float ew3 = edge_w[h * 96 + 64 + kb + 3];
    float den0 = 0.f, den1 = 0.f, den2 = 0.f, den3 = 0.f;
    float acc0 = 0.f, acc1 = 0.f, acc2 = 0.f, acc3 = 0.f;

    int d = g_cnt[n];
    if (d > MAXDEG) d = MAXDEG;
    const int2* sl = g_slot2 + (size_t)n * MAXDEG;
    int2 sa = sl[lane], sb = sl[lane + 32], sc = sl[lane + 64];
    auto get_w0 = [&](int i) {
        int v = (i < 32) ? sa.x : ((i < 64) ? sb.x : sc.x);
        return __shfl_sync(0xffffffffu, v, i & 31);
    };
    auto get_w1 = [&](int i) {
        int v = (i < 32) ? sa.y : ((i < 64) ? sb.y : sc.y);
        return __shfl_sync(0xffffffffu, v, i & 31);
    };

    // pass 1: denominators (fp32) + store exps (fp16x4 per lane, coalesced)
    for (int i = 0; i < d; i++) {
        int w0 = get_w0(i);
        int e  = get_w1(i);
        int s = w0 & 0xFFFF;
        int p = ((w0 >> 16) & 0x7F) + 64;
        float4 as4 = *(const float4*)(g_big + (size_t)s * 384 + 128 + lane * 4);
        float4 ap4 = *(const float4*)(g_Apos + p * 128 + lane * 4);
        float x0 = as4.x + at4.x + ap4.x; x0 = (x0 >= 0.f) ? x0 : 0.2f * x0;
        float x1 = as4.y + at4.y + ap4.y; x1 = (x1 >= 0.f) ? x1 : 0.2f * x1;
        float x2 = as4.z + at4.z + ap4.z; x2 = (x2 >= 0.f) ? x2 : 0.2f * x2;
        float x3 = as4.w + at4.w + ap4.w; x3 = (x3 >= 0.f) ? x3 : 0.2f * x3;
        float e0 = __expf(x0), e1 = __expf(x1), e2 = __expf(x2), e3 = __expf(x3);
        den0 += e0; den1 += e1; den2 += e2; den3 += e3;
        uint2 pk;
        pk.x = pack_h2(e0, e1);
        pk.y = pack_h2(e2, e3);
        g_exh[(size_t)e * 32 + lane] = pk;
    }

    // fold 1/(den+eps) into beta weights (per-lane)
    ew0 = ew0 / (den0 + 1e-12f);
    ew1 = ew1 / (den1 + 1e-12f);
    ew2 = ew2 / (den2 + 1e-12f);
    ew3 = ew3 / (den3 + 1e-12f);

    // pass 2: reload exps, 8-lane reduction, attn, v accumulation
    for (int i = 0; i < d; i++) {
        int w0 = get_w0(i);
        int e  = get_w1(i);          // warp-uniform shfl, BEFORE any divergence
        int s  = w0 & 0xFFFF;
        int dr = (w0 >> 23) & 0x3F;
        int da = ((unsigned)w0 >> 29) & 0x7;
        uint2 pk = g_exh[(size_t)e * 32 + lane];
        float2 f01 = __half22float2(*(const __half2*)&pk.x);
        float2 f23 = __half22float2(*(const __half2*)&pk.y);
        float4 vv4 = *(const float4*)(g_big + (size_t)s * 384 + lane * 4);
        float bdr = g_Bdr[dr * 4 + h];
        float bda = g_Bda[da * 4 + h];
        float pl = f01.x * ew0 + f01.y * ew1 + f23.x * ew2 + f23.y * ew3;
        pl += __shfl_xor_sync(0xffffffffu, pl, 1);
        pl += __shfl_xor_sync(0xffffffffu, pl, 2);
        pl += __shfl_xor_sync(0xffffffffu, pl, 4);
        float y = bdr + bda + pl;
        float es = (y >= 0.f) ? y : 0.2f * y;
        acc0 += vv4.x * es;
        acc1 += vv4.y * es;
        acc2 += vv4.z * es;
        acc3 += vv4.w * es;
        if ((lane & 7) == 0)
            attn[(size_t)e * 4 + h] = es;     // lanes 0/8/16/24 -> one 16B txn
    }

    float4 o = make_float4(f2tff(acc0), f2tff(acc1), f2tff(acc2), f2tff(acc3));
    *(float4*)(g_agg + (size_t)n * 128 + lane * 4) = o;
}

// ------------------- launch -------------------
extern "C" void kernel_launch(void* const* d_in, const int* in_sizes, int n_in,
                              void* d_out, int out_size) {
    const float* inp        = (const float*)d_in[0];
    const int*   relpos     = (const int*)d_in[1];
    // d_in[2] word_rel_pos_edge: unused
    // d_in[3] deprel_ext_edge: unused
    const int*   edge_index = (const int*)d_in[4];
    const int*   deprel     = (const int*)d_in[5];
    const int*   deparc     = (const int*)d_in[6];
    const float* Wkq        = (const float*)d_in[7];
    const float* Wv         = (const float*)d_in[8];
    const float* att_w      = (const float*)d_in[9];
    const float* edge_w     = (const float*)d_in[10];
    const float* Wf         = (const float*)d_in[11];
    const float* final_bias = (const float*)d_in[12];
    const float* E_deprel   = (const float*)d_in[13];
    const float* E_deparc   = (const float*)d_in[14];
    const float* E_pos      = (const float*)d_in[15];

    float* out  = (float*)d_out;             // [N, 256]
    float* attn = out + (size_t)NN * DD;     // [E, 4]

    int prep_n = 384 * 256 + 256 * 128 + 129 * 128 + 256 + 32;   // 147872 > NN
    prep_all_kernel<<<(prep_n + 255) / 256, 256>>>(Wkq, Wv, att_w, Wf,
                                                   E_pos, E_deprel, E_deparc, edge_w);
    scatter_kernel<<<(EE + 255) / 256, 256>>>(edge_index, relpos, deprel, deparc);

    int mt = (NN + 127) / 128;   // 391
    {
        dim3 grid(384 / 64, mt);
        gemm1_kernel<<<grid, 256>>>(inp);
    }

    edge_kernel<<<(NN * 32 + 255) / 256, 256>>>(edge_w, attn);

    {
        dim3 grid(256 / 64, mt);
        gemm2_kernel<<<grid, 256>>>(final_bias, out);
    }
}

// round 15
// speedup vs baseline: 1.0017x; 1.0017x over previous
#include <cuda_runtime.h>
#include <cuda_bf16.h>
#include <cstdint>

#define NN 50000
#define EE 500000
#define DD 256
#define HH 4
#define MAXDEG 96
#define LOG2E 1.4426950408889634f

// ------------------- device scratch (no allocations allowed) -------------------
// 128-col sections in NATURAL order: col = h*32 + k. float4 at lane*4 holds
// (h = lane>>3, k = (lane&7)*4 .. +3).
// A_src / A_tgt sections and Apos are PRE-SCALED by log2e (exp -> ex2 domain).
__device__ float g_WcatT[384 * 256];    // [n=384][k=256], tf32-rounded. rows: 0-127 v | 128-255 A_src*log2e | 256-383 A_tgt*log2e
__device__ float g_WfT[256 * 128];      // [n=256][k=128], tf32-rounded
__device__ float g_big[NN * 384];       // [N, 384] fp32
__device__ float g_Apos[129 * 128];     // [pos][h*32+k] fp32, *log2e
__device__ float g_Bdr[64 * 4];         // [deprel][h]
__device__ float g_Bda[8 * 4];          // [deparc][h]
__device__ float g_agg[NN * 128];       // [n][h*32+dv], tf32-rounded (GEMM2 A operand)
__device__ int   g_cnt[NN];
__device__ int2  g_slot2[NN * MAXDEG];  // packed: w0 = src|relpos<<16|deprel<<23|deparc<<29, w1 = e

// ------------------- helpers -------------------
__device__ __forceinline__ unsigned f2tf(float x) {
    unsigned r;
    asm("cvt.rna.tf32.f32 %0, %1;" : "=r"(r) : "f"(x));
    return r;
}
__device__ __forceinline__ float f2tff(float x) { return __uint_as_float(f2tf(x)); }

__device__ __forceinline__ float ex2(float x) {
    float r;
    asm("ex2.approx.f32 %0, %1;" : "=f"(r) : "f"(x));
    return r;
}

__device__ __forceinline__ void cp_async16(void* smem, const void* gmem, bool pred) {
    unsigned sa = (unsigned)__cvta_generic_to_shared(smem);
    int sz = pred ? 16 : 0;
    asm volatile("cp.async.cg.shared.global [%0], [%1], 16, %2;" :: "r"(sa), "l"(gmem), "r"(sz));
}
__device__ __forceinline__ void cp_commit() { asm volatile("cp.async.commit_group;"); }
__device__ __forceinline__ void cp_wait0() { asm volatile("cp.async.wait_group 0;" ::: "memory"); }

__device__ __forceinline__ void mma_tf32(float* c, const unsigned* a, const unsigned* b) {
    asm volatile(
        "mma.sync.aligned.m16n8k8.row.col.f32.tf32.tf32.f32 "
        "{%0,%1,%2,%3}, {%4,%5,%6,%7}, {%8,%9}, {%0,%1,%2,%3};"
        : "+f"(c[0]), "+f"(c[1]), "+f"(c[2]), "+f"(c[3])
        : "r"(a[0]), "r"(a[1]), "r"(a[2]), "r"(a[3]), "r"(b[0]), "r"(b[1]));
}

// ------------------- merged prep kernel (zero cnt + weights + tables) -------------------
__global__ void prep_all_kernel(const float* __restrict__ Wkq,
                                const float* __restrict__ Wv,
                                const float* __restrict__ att_w,
                                const float* __restrict__ Wf,
                                const float* __restrict__ E_pos,
                                const float* __restrict__ E_deprel,
                                const float* __restrict__ E_deparc,
                                const float* __restrict__ edge_w) {
    int t = blockIdx.x * blockDim.x + threadIdx.x;
    if (t < NN) g_cnt[t] = 0;

    if (t < 384 * 256) {
        int c = t >> 8, d = t & 255;
        int sec = c >> 7;
        int m = c & 127;               // m = h*32 + k (natural)
        int h = m >> 5, k = m & 31;
        float o;
        if (sec == 0) {
            o = Wv[d * 128 + m];
        } else {
            int joff = (sec == 2) ? 32 : 0;
            float s = 0.f;
            #pragma unroll
            for (int j = 0; j < 32; j++)
                s += Wkq[d * 128 + h * 32 + j] * att_w[h * 3072 + (joff + j) * 32 + k];
            o = s * LOG2E;             // ex2 domain
        }
        g_WcatT[c * 256 + d] = f2tff(o);
        return;
    }
    int u = t - 384 * 256;
    if (u < 256 * 128) {
        int c = u & 127, n = u >> 7;
        g_WfT[n * 128 + c] = f2tff(Wf[c * 256 + n]);
        return;
    }
    u -= 256 * 128;
    if (u < 129 * 128) {
        int p = u >> 7, m = u & 127;
        int h = m >> 5, k = m & 31;
        float s = 0.f;
        #pragma unroll
        for (int j = 0; j < 32; j++)
            s += E_pos[p * 32 + j] * att_w[h * 3072 + (64 + j) * 32 + k];
        g_Apos[u] = s * LOG2E;         // ex2 domain
        return;
    }
    u -= 129 * 128;
    if (u < 256) {
        int r = u / 4, h = u % 4;
        float s = 0.f;
        #pragma unroll
        for (int j = 0; j < 32; j++)
            s += E_deprel[r * 32 + j] * edge_w[h * 96 + j];
        g_Bdr[u] = s;
        return;
    }
    u -= 256;
    if (u < 32) {
        int a = u / 4, h = u % 4;
        float s = 0.f;
        #pragma unroll
        for (int j = 0; j < 32; j++)
            s += E_deparc[a * 32 + j] * edge_w[h * 96 + 32 + j];
        g_Bda[u] = s;
    }
}

// ------------------- scatter: pack all per-edge scalars into the slot record -------------------
__global__ void scatter_kernel(const int* __restrict__ edge_index,
                               const int* __restrict__ relpos,
                               const int* __restrict__ deprel,
                               const int* __restrict__ deparc) {
    int e = blockIdx.x * blockDim.x + threadIdx.x;
    if (e >= EE) return;
    int t  = edge_index[EE + e];
    int s  = edge_index[e];
    int rp = relpos[e];          // 0..64 -> 7 bits
    int dr = deprel[e];          // 0..63 -> 6 bits
    int da = deparc[e];          // 0..7  -> 3 bits
    int w0 = s | (rp << 16) | (dr << 23) | (da << 29);
    int r = atomicAdd(&g_cnt[t], 1);
    if (r < MAXDEG) g_slot2[t * MAXDEG + r] = make_int2(w0, e);
}

// ------------------- tf32 mma.sync GEMM: BM=128, BN=128, BK=32, 512 threads -------------------
// 16 warps in 4x4 grid, each computes a 32x32 warp tile. cp.async double-buffered,
// dynamic smem: 2 x (128x32 A) + 2 x (128x32 B) = 64 KB.
template<bool ACVT>
__device__ __forceinline__ void gemm_body(int M, int K,
                                          const float* __restrict__ A, int lda,
                                          const float* __restrict__ BT, int ldbt,
                                          float* __restrict__ C, int ldc,
                                          const float* __restrict__ bias,
                                          float* Asm, float* Bsm) {
    int m0 = blockIdx.y * 128;
    int n0 = blockIdx.x * 128;
    int tid = threadIdx.x;
    int wid = tid >> 5, lane = tid & 31;
    int wm = (wid & 3) * 32;
    int wn = (wid >> 2) * 32;
    int r = lane >> 2, cq = lane & 3;

    float acc[2][4][4];
    #pragma unroll
    for (int i = 0; i < 2; i++)
        #pragma unroll
        for (int j = 0; j < 4; j++)
            #pragma unroll
            for (int q = 0; q < 4; q++) acc[i][j][q] = 0.f;

    auto stage = [&](int buf, int k0) {
        float* Ab = Asm + buf * (128 * 32);
        #pragma unroll
        for (int l = 0; l < 2; l++) {
            int idx = tid + l * 512;               // 1024 chunks
            int row = idx >> 3, c = idx & 7;
            cp_async16(Ab + row * 32 + ((c ^ (row & 7)) << 2),
                       A + (size_t)(m0 + row) * lda + k0 + c * 4, m0 + row < M);
        }
        float* Bb = Bsm + buf * (128 * 32);
        #pragma unroll
        for (int l = 0; l < 2; l++) {
            int idx = tid + l * 512;               // 1024 chunks
            int row = idx >> 3, c = idx & 7;
            cp_async16(Bb + row * 32 + ((c ^ (row & 7)) << 2),
                       BT + (size_t)(n0 + row) * ldbt + k0 + c * 4, true);
        }
    };

    int T = K >> 5;
    stage(0, 0);
    cp_commit();

    for (int t = 0; t < T; t++) {
        cp_wait0();
        __syncthreads();
        if (t + 1 < T) { stage((t + 1) & 1, (t + 1) * 32); cp_commit(); }

        const float* Ab = Asm + (t & 1) * (128 * 32);
        const float* Bb = Bsm + (t & 1) * (128 * 32);
        #pragma unroll
        for (int kf = 0; kf < 4; kf++) {
            int o0 = (((2 * kf) ^ r) << 2) + cq;
            int o1 = (((2 * kf + 1) ^ r) << 2) + cq;
            unsigned afr[2][4], bfr[4][2];
            #pragma unroll
            for (int mf = 0; mf < 2; mf++) {
                const float* b0 = Ab + (wm + mf * 16 + r) * 32;
                const float* b8 = b0 + 8 * 32;
                if (ACVT) {
                    afr[mf][0] = f2tf(b0[o0]); afr[mf][1] = f2tf(b8[o0]);
                    afr[mf][2] = f2tf(b0[o1]); afr[mf][3] = f2tf(b8[o1]);
                } else {
                    afr[mf][0] = __float_as_uint(b0[o0]); afr[mf][1] = __float_as_uint(b8[o0]);
                    afr[mf][2] = __float_as_uint(b0[o1]); afr[mf][3] = __float_as_uint(b8[o1]);
                }
            }
            #pragma unroll
            for (int nf = 0; nf < 4; nf++) {
                const float* bb = Bb + (wn + nf * 8 + r) * 32;
                bfr[nf][0] = __float_as_uint(bb[o0]);
                bfr[nf][1] = __float_as_uint(bb[o1]);
            }
            #pragma unroll
            for (int mf = 0; mf < 2; mf++)
                #pragma unroll
                for (int nf = 0; nf < 4; nf++)
                    mma_tf32(acc[mf][nf], afr[mf], bfr[nf]);
        }
        __syncthreads();
    }

    #pragma unroll
    for (int mf = 0; mf < 2; mf++) {
        #pragma unroll
        for (int nf = 0; nf < 4; nf++) {
            int col = n0 + wn + nf * 8 + cq * 2;
            float b0 = 0.f, b1 = 0.f;
            if (bias) { b0 = bias[col]; b1 = bias[col + 1]; }
            int row0 = m0 + wm + mf * 16 + r;
            if (row0 < M)
                *(float2*)(C + (size_t)row0 * ldc + col) =
                    make_float2(acc[mf][nf][0] + b0, acc[mf][nf][1] + b1);
            int row1 = row0 + 8;
            if (row1 < M)
                *(float2*)(C + (size_t)row1 * ldc + col) =
                    make_float2(acc[mf][nf][2] + b0, acc[mf][nf][3] + b1);
        }
    }
}

#define GEMM_SMEM (4 * 128 * 32 * 4)   // 65536 bytes

__global__ void gemm1_kernel(const float* __restrict__ inp) {
    extern __shared__ float sm[];
    gemm_body<true>(NN, 256, inp, 256, g_WcatT, 256, g_big, 384, nullptr,
                    sm, sm + 2 * 128 * 32);
}

__global__ void gemm2_kernel(const float* __restrict__ bias, float* __restrict__ out) {
    extern __shared__ float sm[];
    gemm_body<false>(NN, 128, g_agg, 128, g_WfT, 128, out, 256, bias,
                     sm, sm + 2 * 128 * 32);
}

// ------------------- edge/attention kernel: one warp per target node -------------------
// Round-12 proven structure; scores live in ex2 domain (tables pre-scaled by log2e).
__global__ void edge_kernel(const float* __restrict__ edge_w,
                            float* __restrict__ attn) {
    int warp = (blockIdx.x * blockDim.x + threadIdx.x) >> 5;
    int lane = threadIdx.x & 31;
    if (warp >= NN) return;
    int n = warp;
    int h = lane >> 3;
    int kb = (lane & 7) * 4;

    float4 at4 = *(const float4*)(g_big + (size_t)n * 384 + 256 + lane * 4);
    float ew0 = edge_w[h * 96 + 64 + kb + 0];
    float ew1 = edge_w[h * 96 + 64 + kb + 1];
    float ew2 = edge_w[h * 96 + 64 + kb + 2];
    float ew3 = edge_w[h * 96 + 64 + kb + 3];
    float den0 = 0.f, den1 = 0.f, den2 = 0.f, den3 = 0.f;
    float acc0 = 0.f, acc1 = 0.f, acc2 = 0.f, acc3 = 0.f;

    int d = g_cnt[n];
    if (d > MAXDEG) d = MAXDEG;
    const int2* sl = g_slot2 + (size_t)n * MAXDEG;
    int2 sa = sl[lane], sb = sl[lane + 32], sc = sl[lane + 64];
    auto get_w0 = [&](int i) {
        int v = (i < 32) ? sa.x : ((i < 64) ? sb.x : sc.x);
        return __shfl_sync(0xffffffffu, v, i & 31);
    };
    auto get_w1 = [&](int i) {
        int v = (i < 32) ? sa.y : ((i < 64) ? sb.y : sc.y);
        return __shfl_sync(0xffffffffu, v, i & 31);
    };

    // pass 1: denominators (per-lane, no reduction). x in ex2 domain.
    for (int i = 0; i < d; i++) {
        int w0 = get_w0(i);
        int s = w0 & 0xFFFF;
        int p = ((w0 >> 16) & 0x7F) + 64;
        float4 as4 = *(const float4*)(g_big + (size_t)s * 384 + 128 + lane * 4);
        float4 ap4 = *(const float4*)(g_Apos + p * 128 + lane * 4);
        float x0 = as4.x + at4.x + ap4.x; x0 = fmaxf(x0, 0.2f * x0);
        float x1 = as4.y + at4.y + ap4.y; x1 = fmaxf(x1, 0.2f * x1);
        float x2 = as4.z + at4.z + ap4.z; x2 = fmaxf(x2, 0.2f * x2);
        float x3 = as4.w + at4.w + ap4.w; x3 = fmaxf(x3, 0.2f * x3);
        den0 += ex2(x0); den1 += ex2(x1);
        den2 += ex2(x2); den3 += ex2(x3);
    }

    // fold 1/(den+eps) into beta weights (per-lane)
    ew0 = ew0 / (den0 + 1e-12f);
    ew1 = ew1 / (den1 + 1e-12f);
    ew2 = ew2 / (den2 + 1e-12f);
    ew3 = ew3 / (den3 + 1e-12f);

    // pass 2: recompute exps, 8-lane reduction, attn, v accumulation
    for (int i = 0; i < d; i++) {
        int w0 = get_w0(i);
        int e  = get_w1(i);          // warp-uniform shfl, BEFORE any divergence
        int s  = w0 & 0xFFFF;
        int p  = ((w0 >> 16) & 0x7F) + 64;
        int dr = (w0 >> 23) & 0x3F;
        int da = ((unsigned)w0 >> 29) & 0x7;
        float4 as4 = *(const float4*)(g_big + (size_t)s * 384 + 128 + lane * 4);
        float4 ap4 = *(const float4*)(g_Apos + p * 128 + lane * 4);
        float4 vv4 = *(const float4*)(g_big + (size_t)s * 384 + lane * 4);
        float bdr = g_Bdr[dr * 4 + h];
        float bda = g_Bda[da * 4 + h];
        float x0 = as4.x + at4.x + ap4.x; x0 = fmaxf(x0, 0.2f * x0);
        float x1 = as4.y + at4.y + ap4.y; x1 = fmaxf(x1, 0.2f * x1);
        float x2 = as4.z + at4.z + ap4.z; x2 = fmaxf(x2, 0.2f * x2);
        float x3 = as4.w + at4.w + ap4.w; x3 = fmaxf(x3, 0.2f * x3);
        float pl = ex2(x0) * ew0 + ex2(x1) * ew1
                 + ex2(x2) * ew2 + ex2(x3) * ew3;
        pl += __shfl_xor_sync(0xffffffffu, pl, 1);
        pl += __shfl_xor_sync(0xffffffffu, pl, 2);
        pl += __shfl_xor_sync(0xffffffffu, pl, 4);
        float y = bdr + bda + pl;
        float es = fmaxf(y, 0.2f * y);
        acc0 += vv4.x * es;
        acc1 += vv4.y * es;
        acc2 += vv4.z * es;
        acc3 += vv4.w * es;
        if ((lane & 7) == 0)
            attn[(size_t)e * 4 + h] = es;     // lanes 0/8/16/24 -> one 16B txn
    }

    float4 o = make_float4(f2tff(acc0), f2tff(acc1), f2tff(acc2), f2tff(acc3));
    *(float4*)(g_agg + (size_t)n * 128 + lane * 4) = o;
}

// ------------------- launch -------------------
extern "C" void kernel_launch(void* const* d_in, const int* in_sizes, int n_in,
                              void* d_out, int out_size) {
    const float* inp        = (const float*)d_in[0];
    const int*   relpos     = (const int*)d_in[1];
    // d_in[2] word_rel_pos_edge: unused
    // d_in[3] deprel_ext_edge: unused
    const int*   edge_index = (const int*)d_in[4];
    const int*   deprel     = (const int*)d_in[5];
    const int*   deparc     = (const int*)d_in[6];
    const float* Wkq        = (const float*)d_in[7];
    const float* Wv         = (const float*)d_in[8];
    const float* att_w      = (const float*)d_in[9];
    const float* edge_w     = (const float*)d_in[10];
    const float* Wf         = (const float*)d_in[11];
    const float* final_bias = (const float*)d_in[12];
    const float* E_deprel   = (const float*)d_in[13];
    const float* E_deparc   = (const float*)d_in[14];
    const float* E_pos      = (const float*)d_in[15];

    float* out  = (float*)d_out;             // [N, 256]
    float* attn = out + (size_t)NN * DD;     // [E, 4]

    cudaFuncSetAttribute((const void*)gemm1_kernel,
                         cudaFuncAttributeMaxDynamicSharedMemorySize, GEMM_SMEM);
    cudaFuncSetAttribute((const void*)gemm2_kernel,
                         cudaFuncAttributeMaxDynamicSharedMemorySize, GEMM_SMEM);

    int prep_n = 384 * 256 + 256 * 128 + 129 * 128 + 256 + 32;   // 147872 > NN
    prep_all_kernel<<<(prep_n + 255) / 256, 256>>>(Wkq, Wv, att_w, Wf,
                                                   E_pos, E_deprel, E_deparc, edge_w);
    scatter_kernel<<<(EE + 255) / 256, 256>>>(edge_index, relpos, deprel, deparc);

    int mt = (NN + 127) / 128;   // 391
    {
        dim3 grid(384 / 128, mt);
        gemm1_kernel<<<grid, 512, GEMM_SMEM>>>(inp);
    }

    edge_kernel<<<(NN * 32 + 255) / 256, 256>>>(edge_w, attn);

    {
        dim3 grid(256 / 128, mt);
        gemm2_kernel<<<grid, 512, GEMM_SMEM>>>(final_bias, out);
    }
}

// round 16
// speedup vs baseline: 1.0498x; 1.0480x over previous
#include <cuda_runtime.h>
#include <cuda_bf16.h>
#include <cstdint>

#define NN 50000
#define EE 500000
#define DD 256
#define HH 4
#define MAXDEG 96
#define LOG2E 1.4426950408889634f

// ------------------- device scratch (no allocations allowed) -------------------
// 128-col sections in NATURAL order: col = h*32 + k. float4 at lane*4 holds
// (h = lane>>3, k = (lane&7)*4 .. +3).
// A_src / A_tgt sections and Apos are PRE-SCALED by log2e (exp -> ex2 domain).
__device__ float g_WcatT[384 * 256];    // [n=384][k=256], tf32-rounded. rows: 0-127 v | 128-255 A_src*log2e | 256-383 A_tgt*log2e
__device__ float g_WfT[256 * 128];      // [n=256][k=128], tf32-rounded
__device__ float g_big[NN * 384];       // [N, 384] fp32
__device__ float g_Apos[129 * 128];     // [pos][h*32+k] fp32, *log2e
__device__ float g_Bdr[64 * 4];         // [deprel][h]
__device__ float g_Bda[8 * 4];          // [deparc][h]
__device__ float g_agg[NN * 128];       // [n][h*32+dv], tf32-rounded (GEMM2 A operand)
__device__ int   g_cnt[NN];
__device__ int2  g_slot2[NN * MAXDEG];  // packed: w0 = src|relpos<<16|deprel<<23|deparc<<29, w1 = e

// ------------------- helpers -------------------
__device__ __forceinline__ unsigned f2tf(float x) {
    unsigned r;
    asm("cvt.rna.tf32.f32 %0, %1;" : "=r"(r) : "f"(x));
    return r;
}
__device__ __forceinline__ float f2tff(float x) { return __uint_as_float(f2tf(x)); }

__device__ __forceinline__ float ex2(float x) {
    float r;
    asm("ex2.approx.f32 %0, %1;" : "=f"(r) : "f"(x));
    return r;
}

__device__ __forceinline__ void cp_async16(void* smem, const void* gmem, bool pred) {
    unsigned sa = (unsigned)__cvta_generic_to_shared(smem);
    int sz = pred ? 16 : 0;
    asm volatile("cp.async.cg.shared.global [%0], [%1], 16, %2;" :: "r"(sa), "l"(gmem), "r"(sz));
}
__device__ __forceinline__ void cp_commit() { asm volatile("cp.async.commit_group;"); }
__device__ __forceinline__ void cp_wait0() { asm volatile("cp.async.wait_group 0;" ::: "memory"); }

__device__ __forceinline__ void mma_tf32(float* c, const unsigned* a, const unsigned* b) {
    asm volatile(
        "mma.sync.aligned.m16n8k8.row.col.f32.tf32.tf32.f32 "
        "{%0,%1,%2,%3}, {%4,%5,%6,%7}, {%8,%9}, {%0,%1,%2,%3};"
        : "+f"(c[0]), "+f"(c[1]), "+f"(c[2]), "+f"(c[3])
        : "r"(a[0]), "r"(a[1]), "r"(a[2]), "r"(a[3]), "r"(b[0]), "r"(b[1]));
}

// ------------------- merged prep kernel (zero cnt + weights + tables) -------------------
__global__ void prep_all_kernel(const float* __restrict__ Wkq,
                                const float* __restrict__ Wv,
                                const float* __restrict__ att_w,
                                const float* __restrict__ Wf,
                                const float* __restrict__ E_pos,
                                const float* __restrict__ E_deprel,
                                const float* __restrict__ E_deparc,
                                const float* __restrict__ edge_w) {
    int t = blockIdx.x * blockDim.x + threadIdx.x;
    if (t < NN) g_cnt[t] = 0;

    if (t < 384 * 256) {
        int c = t >> 8, d = t & 255;
        int sec = c >> 7;
        int m = c & 127;               // m = h*32 + k (natural)
        int h = m >> 5, k = m & 31;
        float o;
        if (sec == 0) {
            o = Wv[d * 128 + m];
        } else {
            int joff = (sec == 2) ? 32 : 0;
            float s = 0.f;
            #pragma unroll
            for (int j = 0; j < 32; j++)
                s += Wkq[d * 128 + h * 32 + j] * att_w[h * 3072 + (joff + j) * 32 + k];
            o = s * LOG2E;             // ex2 domain
        }
        g_WcatT[c * 256 + d] = f2tff(o);
        return;
    }
    int u = t - 384 * 256;
    if (u < 256 * 128) {
        int c = u & 127, n = u >> 7;
        g_WfT[n * 128 + c] = f2tff(Wf[c * 256 + n]);
        return;
    }
    u -= 256 * 128;
    if (u < 129 * 128) {
        int p = u >> 7, m = u & 127;
        int h = m >> 5, k = m & 31;
        float s = 0.f;
        #pragma unroll
        for (int j = 0; j < 32; j++)
            s += E_pos[p * 32 + j] * att_w[h * 3072 + (64 + j) * 32 + k];
        g_Apos[u] = s * LOG2E;         // ex2 domain
        return;
    }
    u -= 129 * 128;
    if (u < 256) {
        int r = u / 4, h = u % 4;
        float s = 0.f;
        #pragma unroll
        for (int j = 0; j < 32; j++)
            s += E_deprel[r * 32 + j] * edge_w[h * 96 + j];
        g_Bdr[u] = s;
        return;
    }
    u -= 256;
    if (u < 32) {
        int a = u / 4, h = u % 4;
        float s = 0.f;
        #pragma unroll
        for (int j = 0; j < 32; j++)
            s += E_deparc[a * 32 + j] * edge_w[h * 96 + 32 + j];
        g_Bda[u] = s;
    }
}

// ------------------- scatter: pack all per-edge scalars into the slot record -------------------
__global__ void scatter_kernel(const int* __restrict__ edge_index,
                               const int* __restrict__ relpos,
                               const int* __restrict__ deprel,
                               const int* __restrict__ deparc) {
    int e = blockIdx.x * blockDim.x + threadIdx.x;
    if (e >= EE) return;
    int t  = edge_index[EE + e];
    int s  = edge_index[e];
    int rp = relpos[e];          // 0..64 -> 7 bits
    int dr = deprel[e];          // 0..63 -> 6 bits
    int da = deparc[e];          // 0..7  -> 3 bits
    int w0 = s | (rp << 16) | (dr << 23) | (da << 29);
    int r = atomicAdd(&g_cnt[t], 1);
    if (r < MAXDEG) g_slot2[t * MAXDEG + r] = make_int2(w0, e);
}

// ------------------- tf32 mma.sync GEMM, cp.async double-buffered (round-12 proven) -------------------
template<bool ACVT>
__device__ __forceinline__ void gemm_body(int M, int K,
                                          const float* __restrict__ A, int lda,
                                          const float* __restrict__ BT, int ldbt,
                                          float* __restrict__ C, int ldc,
                                          const float* __restrict__ bias,
                                          float (*As)[128 * 32], float (*Bs)[64 * 32]) {
    int m0 = blockIdx.y * 128;
    int n0 = blockIdx.x * 64;
    int tid = threadIdx.x;
    int wid = tid >> 5, lane = tid & 31;
    int wm = (wid & 3) * 32;
    int wn = (wid >> 2) * 32;
    int r = lane >> 2, cq = lane & 3;

    float acc[2][4][4];
    #pragma unroll
    for (int i = 0; i < 2; i++)
        #pragma unroll
        for (int j = 0; j < 4; j++)
            #pragma unroll
            for (int q = 0; q < 4; q++) acc[i][j][q] = 0.f;

    auto stage = [&](int buf, int k0) {
        #pragma unroll
        for (int l = 0; l < 4; l++) {
            int idx = tid + l * 256;
            int row = idx >> 3, c = idx & 7;
            float* dst = As[buf] + row * 32 + ((c ^ (row & 7)) << 2);
            cp_async16(dst, A + (size_t)(m0 + row) * lda + k0 + c * 4, m0 + row < M);
        }
        #pragma unroll
        for (int l = 0; l < 2; l++) {
            int idx = tid + l * 256;
            int row = idx >> 3, c = idx & 7;
            float* dst = Bs[buf] + row * 32 + ((c ^ (row & 7)) << 2);
            cp_async16(dst, BT + (size_t)(n0 + row) * ldbt + k0 + c * 4, true);
        }
    };

    int T = K >> 5;
    stage(0, 0);
    cp_commit();

    for (int t = 0; t < T; t++) {
        cp_wait0();
        __syncthreads();
        if (t + 1 < T) { stage((t + 1) & 1, (t + 1) * 32); cp_commit(); }

        const float* Ab = As[t & 1];
        const float* Bb = Bs[t & 1];
        #pragma unroll
        for (int kf = 0; kf < 4; kf++) {
            int o0 = (((2 * kf) ^ r) << 2) + cq;
            int o1 = (((2 * kf + 1) ^ r) << 2) + cq;
            unsigned afr[2][4], bfr[4][2];
            #pragma unroll
            for (int mf = 0; mf < 2; mf++) {
                const float* b0 = Ab + (wm + mf * 16 + r) * 32;
                const float* b8 = b0 + 8 * 32;
                if (ACVT) {
                    afr[mf][0] = f2tf(b0[o0]); afr[mf][1] = f2tf(b8[o0]);
                    afr[mf][2] = f2tf(b0[o1]); afr[mf][3] = f2tf(b8[o1]);
                } else {
                    afr[mf][0] = __float_as_uint(b0[o0]); afr[mf][1] = __float_as_uint(b8[o0]);
                    afr[mf][2] = __float_as_uint(b0[o1]); afr[mf][3] = __float_as_uint(b8[o1]);
                }
            }
            #pragma unroll
            for (int nf = 0; nf < 4; nf++) {
                const float* bb = Bb + (wn + nf * 8 + r) * 32;
                bfr[nf][0] = __float_as_uint(bb[o0]);
                bfr[nf][1] = __float_as_uint(bb[o1]);
            }
            #pragma unroll
            for (int mf = 0; mf < 2; mf++)
                #pragma unroll
                for (int nf = 0; nf < 4; nf++)
                    mma_tf32(acc[mf][nf], afr[mf], bfr[nf]);
        }
        __syncthreads();
    }

    #pragma unroll
    for (int mf = 0; mf < 2; mf++) {
        #pragma unroll
        for (int nf = 0; nf < 4; nf++) {
            int col = n0 + wn + nf * 8 + cq * 2;
            float b0 = 0.f, b1 = 0.f;
            if (bias) { b0 = bias[col]; b1 = bias[col + 1]; }
            int row0 = m0 + wm + mf * 16 + r;
            if (row0 < M)
                *(float2*)(C + (size_t)row0 * ldc + col) =
                    make_float2(acc[mf][nf][0] + b0, acc[mf][nf][1] + b1);
            int row1 = row0 + 8;
            if (row1 < M)
                *(float2*)(C + (size_t)row1 * ldc + col) =
                    make_float2(acc[mf][nf][2] + b0, acc[mf][nf][3] + b1);
        }
    }
}

__global__ void gemm1_kernel(const float* __restrict__ inp) {
    __shared__ float As[2][128 * 32];
    __shared__ float Bs[2][64 * 32];
    gemm_body<true>(NN, 256, inp, 256, g_WcatT, 256, g_big, 384, nullptr, As, Bs);
}

__global__ void gemm2_kernel(const float* __restrict__ bias, float* __restrict__ out) {
    __shared__ float As[2][128 * 32];
    __shared__ float Bs[2][64 * 32];
    gemm_body<false>(NN, 128, g_agg, 128, g_WfT, 128, out, 256, bias, As, Bs);
}

// ------------------- edge/attention kernel: one warp per target node -------------------
// Natural [h*32+k] layout; packed slots; scores in ex2 domain (tables pre-scaled).
__global__ void edge_kernel(const float* __restrict__ edge_w,
                            float* __restrict__ attn) {
    int warp = (blockIdx.x * blockDim.x + threadIdx.x) >> 5;
    int lane = threadIdx.x & 31;
    if (warp >= NN) return;
    int n = warp;
    int h = lane >> 3;
    int kb = (lane & 7) * 4;

    float4 at4 = *(const float4*)(g_big + (size_t)n * 384 + 256 + lane * 4);
    float ew0 = edge_w[h * 96 + 64 + kb + 0];
    float ew1 = edge_w[h * 96 + 64 + kb + 1];
    float ew2 = edge_w[h * 96 + 64 + kb + 2];
    float ew3 = edge_w[h * 96 + 64 + kb + 3];
    float den0 = 0.f, den1 = 0.f, den2 = 0.f, den3 = 0.f;
    float acc0 = 0.f, acc1 = 0.f, acc2 = 0.f, acc3 = 0.f;

    int d = g_cnt[n];
    if (d > MAXDEG) d = MAXDEG;
    const int2* sl = g_slot2 + (size_t)n * MAXDEG;
    int2 sa = sl[lane], sb = sl[lane + 32], sc = sl[lane + 64];
    auto get_w0 = [&](int i) {
        int v = (i < 32) ? sa.x : ((i < 64) ? sb.x : sc.x);
        return __shfl_sync(0xffffffffu, v, i & 31);
    };
    auto get_w1 = [&](int i) {
        int v = (i < 32) ? sa.y : ((i < 64) ? sb.y : sc.y);
        return __shfl_sync(0xffffffffu, v, i & 31);
    };

    // pass 1: denominators (per-lane, no reduction). x in ex2 domain.
    for (int i = 0; i < d; i++) {
        int w0 = get_w0(i);
        int s = w0 & 0xFFFF;
        int p = ((w0 >> 16) & 0x7F) + 64;
        float4 as4 = *(const float4*)(g_big + (size_t)s * 384 + 128 + lane * 4);
        float4 ap4 = *(const float4*)(g_Apos + p * 128 + lane * 4);
        float x0 = as4.x + at4.x + ap4.x; x0 = fmaxf(x0, 0.2f * x0);
        float x1 = as4.y + at4.y + ap4.y; x1 = fmaxf(x1, 0.2f * x1);
        float x2 = as4.z + at4.z + ap4.z; x2 = fmaxf(x2, 0.2f * x2);
        float x3 = as4.w + at4.w + ap4.w; x3 = fmaxf(x3, 0.2f * x3);
        den0 += ex2(x0); den1 += ex2(x1);
        den2 += ex2(x2); den3 += ex2(x3);
    }

    // fold 1/(den+eps) into beta weights (per-lane)
    ew0 = ew0 / (den0 + 1e-12f);
    ew1 = ew1 / (den1 + 1e-12f);
    ew2 = ew2 / (den2 + 1e-12f);
    ew3 = ew3 / (den3 + 1e-12f);

    // pass 2: recompute exps, 8-lane reduction, attn, v accumulation
    for (int i = 0; i < d; i++) {
        int w0 = get_w0(i);
        int e  = get_w1(i);          // warp-uniform shfl, BEFORE any divergence
        int s  = w0 & 0xFFFF;
        int p  = ((w0 >> 16) & 0x7F) + 64;
        int dr = (w0 >> 23) & 0x3F;
        int da = ((unsigned)w0 >> 29) & 0x7;
        float4 as4 = *(const float4*)(g_big + (size_t)s * 384 + 128 + lane * 4);
        float4 ap4 = *(const float4*)(g_Apos + p * 128 + lane * 4);
        float4 vv4 = *(const float4*)(g_big + (size_t)s * 384 + lane * 4);
        float bdr = g_Bdr[dr * 4 + h];
        float bda = g_Bda[da * 4 + h];
        float x0 = as4.x + at4.x + ap4.x; x0 = fmaxf(x0, 0.2f * x0);
        float x1 = as4.y + at4.y + ap4.y; x1 = fmaxf(x1, 0.2f * x1);
        float x2 = as4.z + at4.z + ap4.z; x2 = fmaxf(x2, 0.2f * x2);
        float x3 = as4.w + at4.w + ap4.w; x3 = fmaxf(x3, 0.2f * x3);
        float pl = ex2(x0) * ew0 + ex2(x1) * ew1
                 + ex2(x2) * ew2 + ex2(x3) * ew3;
        pl += __shfl_xor_sync(0xffffffffu, pl, 1);
        pl += __shfl_xor_sync(0xffffffffu, pl, 2);
        pl += __shfl_xor_sync(0xffffffffu, pl, 4);
        float y = bdr + bda + pl;
        float es = fmaxf(y, 0.2f * y);
        acc0 += vv4.x * es;
        acc1 += vv4.y * es;
        acc2 += vv4.z * es;
        acc3 += vv4.w * es;
        if ((lane & 7) == 0)
            attn[(size_t)e * 4 + h] = es;     // lanes 0/8/16/24 -> one 16B txn
    }

    float4 o = make_float4(f2tff(acc0), f2tff(acc1), f2tff(acc2), f2tff(acc3));
    *(float4*)(g_agg + (size_t)n * 128 + lane * 4) = o;
}

// ------------------- launch -------------------
extern "C" void kernel_launch(void* const* d_in, const int* in_sizes, int n_in,
                              void* d_out, int out_size) {
    const float* inp        = (const float*)d_in[0];
    const int*   relpos     = (const int*)d_in[1];
    // d_in[2] word_rel_pos_edge: unused
    // d_in[3] deprel_ext_edge: unused
    const int*   edge_index = (const int*)d_in[4];
    const int*   deprel     = (const int*)d_in[5];
    const int*   deparc     = (const int*)d_in[6];
    const float* Wkq        = (const float*)d_in[7];
    const float* Wv         = (const float*)d_in[8];
    const float* att_w      = (const float*)d_in[9];
    const float* edge_w     = (const float*)d_in[10];
    const float* Wf         = (const float*)d_in[11];
    const float* final_bias = (const float*)d_in[12];
    const float* E_deprel   = (const float*)d_in[13];
    const float* E_deparc   = (const float*)d_in[14];
    const float* E_pos      = (const float*)d_in[15];

    float* out  = (float*)d_out;             // [N, 256]
    float* attn = out + (size_t)NN * DD;     // [E, 4]

    int prep_n = 384 * 256 + 256 * 128 + 129 * 128 + 256 + 32;   // 147872 > NN
    prep_all_kernel<<<(prep_n + 255) / 256, 256>>>(Wkq, Wv, att_w, Wf,
                                                   E_pos, E_deprel, E_deparc, edge_w);
    scatter_kernel<<<(EE + 255) / 256, 256>>>(edge_index, relpos, deprel, deparc);

    int mt = (NN + 127) / 128;   // 391
    {
        dim3 grid(384 / 64, mt);
        gemm1_kernel<<<grid, 256>>>(inp);
    }

    edge_kernel<<<(NN * 32 + 255) / 256, 256>>>(edge_w, attn);

    {
        dim3 grid(256 / 64, mt);
        gemm2_kernel<<<grid, 256>>>(final_bias, out);
    }
}

// round 17
// speedup vs baseline: 1.0506x; 1.0008x over previous
#include <cuda_runtime.h>
#include <cuda_bf16.h>
#include <cuda_fp16.h>
#include <cstdint>

#define NN 50000
#define EE 500000
#define DD 256
#define HH 4
#define MAXDEG 96
#define CACHED 16
#define LOG2E 1.4426950408889634f

// ------------------- device scratch (no allocations allowed) -------------------
// 128-col sections in NATURAL order: col = h*32 + k. float4 at lane*4 holds
// (h = lane>>3, k = (lane&7)*4 .. +3).
// A_src / A_tgt sections and Apos are PRE-SCALED by log2e (exp -> ex2 domain).
__device__ float g_WcatT[384 * 256];    // [n=384][k=256], tf32-rounded. rows: 0-127 v | 128-255 A_src*log2e | 256-383 A_tgt*log2e
__device__ float g_WfT[256 * 128];      // [n=256][k=128], tf32-rounded
__device__ float g_big[NN * 384];       // [N, 384] fp32
__device__ float g_Apos[129 * 128];     // [pos][h*32+k] fp32, *log2e
__device__ float g_Bdr[64 * 4];         // [deprel][h]
__device__ float g_Bda[8 * 4];          // [deparc][h]
__device__ float g_agg[NN * 128];       // [n][h*32+dv], tf32-rounded (GEMM2 A operand)
__device__ int   g_cnt[NN];
__device__ int2  g_slot2[NN * MAXDEG];  // packed: w0 = src|relpos<<16|deprel<<23|deparc<<29, w1 = e

// ------------------- helpers -------------------
__device__ __forceinline__ unsigned f2tf(float x) {
    unsigned r;
    asm("cvt.rna.tf32.f32 %0, %1;" : "=r"(r) : "f"(x));
    return r;
}
__device__ __forceinline__ float f2tff(float x) { return __uint_as_float(f2tf(x)); }

__device__ __forceinline__ float ex2(float x) {
    float r;
    asm("ex2.approx.f32 %0, %1;" : "=f"(r) : "f"(x));
    return r;
}

__device__ __forceinline__ unsigned pack_h2(float lo, float hi) {
    unsigned r;
    asm("cvt.rn.f16x2.f32 %0, %1, %2;" : "=r"(r) : "f"(hi), "f"(lo));
    return r;
}

__device__ __forceinline__ void cp_async16(void* smem, const void* gmem, bool pred) {
    unsigned sa = (unsigned)__cvta_generic_to_shared(smem);
    int sz = pred ? 16 : 0;
    asm volatile("cp.async.cg.shared.global [%0], [%1], 16, %2;" :: "r"(sa), "l"(gmem), "r"(sz));
}
__device__ __forceinline__ void cp_commit() { asm volatile("cp.async.commit_group;"); }
__device__ __forceinline__ void cp_wait0() { asm volatile("cp.async.wait_group 0;" ::: "memory"); }

__device__ __forceinline__ void mma_tf32(float* c, const unsigned* a, const unsigned* b) {
    asm volatile(
        "mma.sync.aligned.m16n8k8.row.col.f32.tf32.tf32.f32 "
        "{%0,%1,%2,%3}, {%4,%5,%6,%7}, {%8,%9}, {%0,%1,%2,%3};"
        : "+f"(c[0]), "+f"(c[1]), "+f"(c[2]), "+f"(c[3])
        : "r"(a[0]), "r"(a[1]), "r"(a[2]), "r"(a[3]), "r"(b[0]), "r"(b[1]));
}

// ------------------- merged prep kernel (zero cnt + weights + tables) -------------------
__global__ void prep_all_kernel(const float* __restrict__ Wkq,
                                const float* __restrict__ Wv,
                                const float* __restrict__ att_w,
                                const float* __restrict__ Wf,
                                const float* __restrict__ E_pos,
                                const float* __restrict__ E_deprel,
                                const float* __restrict__ E_deparc,
                                const float* __restrict__ edge_w) {
    int t = blockIdx.x * blockDim.x + threadIdx.x;
    if (t < NN) g_cnt[t] = 0;

    if (t < 384 * 256) {
        int c = t >> 8, d = t & 255;
        int sec = c >> 7;
        int m = c & 127;               // m = h*32 + k (natural)
        int h = m >> 5, k = m & 31;
        float o;
        if (sec == 0) {
            o = Wv[d * 128 + m];
        } else {
            int joff = (sec == 2) ? 32 : 0;
            float s = 0.f;
            #pragma unroll
            for (int j = 0; j < 32; j++)
                s += Wkq[d * 128 + h * 32 + j] * att_w[h * 3072 + (joff + j) * 32 + k];
            o = s * LOG2E;             // ex2 domain
        }
        g_WcatT[c * 256 + d] = f2tff(o);
        return;
    }
    int u = t - 384 * 256;
    if (u < 256 * 128) {
        int c = u & 127, n = u >> 7;
        g_WfT[n * 128 + c] = f2tff(Wf[c * 256 + n]);
        return;
    }
    u -= 256 * 128;
    if (u < 129 * 128) {
        int p = u >> 7, m = u & 127;
        int h = m >> 5, k = m & 31;
        float s = 0.f;
        #pragma unroll
        for (int j = 0; j < 32; j++)
            s += E_pos[p * 32 + j] * att_w[h * 3072 + (64 + j) * 32 + k];
        g_Apos[u] = s * LOG2E;         // ex2 domain
        return;
    }
    u -= 129 * 128;
    if (u < 256) {
        int r = u / 4, h = u % 4;
        float s = 0.f;
        #pragma unroll
        for (int j = 0; j < 32; j++)
            s += E_deprel[r * 32 + j] * edge_w[h * 96 + j];
        g_Bdr[u] = s;
        return;
    }
    u -= 256;
    if (u < 32) {
        int a = u / 4, h = u % 4;
        float s = 0.f;
        #pragma unroll
        for (int j = 0; j < 32; j++)
            s += E_deparc[a * 32 + j] * edge_w[h * 96 + 32 + j];
        g_Bda[u] = s;
    }
}

// ------------------- scatter: pack all per-edge scalars into the slot record -------------------
__global__ void scatter_kernel(const int* __restrict__ edge_index,
                               const int* __restrict__ relpos,
                               const int* __restrict__ deprel,
                               const int* __restrict__ deparc) {
    int e = blockIdx.x * blockDim.x + threadIdx.x;
    if (e >= EE) return;
    int t  = edge_index[EE + e];
    int s  = edge_index[e];
    int rp = relpos[e];          // 0..64 -> 7 bits
    int dr = deprel[e];          // 0..63 -> 6 bits
    int da = deparc[e];          // 0..7  -> 3 bits
    int w0 = s | (rp << 16) | (dr << 23) | (da << 29);
    int r = atomicAdd(&g_cnt[t], 1);
    if (r < MAXDEG) g_slot2[t * MAXDEG + r] = make_int2(w0, e);
}

// ------------------- tf32 mma.sync GEMM, cp.async double-buffered (round-12 proven) -------------------
template<bool ACVT>
__device__ __forceinline__ void gemm_body(int M, int K,
                                          const float* __restrict__ A, int lda,
                                          const float* __restrict__ BT, int ldbt,
                                          float* __restrict__ C, int ldc,
                                          const float* __restrict__ bias,
                                          float (*As)[128 * 32], float (*Bs)[64 * 32]) {
    int m0 = blockIdx.y * 128;
    int n0 = blockIdx.x * 64;
    int tid = threadIdx.x;
    int wid = tid >> 5, lane = tid & 31;
    int wm = (wid & 3) * 32;
    int wn = (wid >> 2) * 32;
    int r = lane >> 2, cq = lane & 3;

    float acc[2][4][4];
    #pragma unroll
    for (int i = 0; i < 2; i++)
        #pragma unroll
        for (int j = 0; j < 4; j++)
            #pragma unroll
            for (int q = 0; q < 4; q++) acc[i][j][q] = 0.f;

    auto stage = [&](int buf, int k0) {
        #pragma unroll
        for (int l = 0; l < 4; l++) {
            int idx = tid + l * 256;
            int row = idx >> 3, c = idx & 7;
            float* dst = As[buf] + row * 32 + ((c ^ (row & 7)) << 2);
            cp_async16(dst, A + (size_t)(m0 + row) * lda + k0 + c * 4, m0 + row < M);
        }
        #pragma unroll
        for (int l = 0; l < 2; l++) {
            int idx = tid + l * 256;
            int row = idx >> 3, c = idx & 7;
            float* dst = Bs[buf] + row * 32 + ((c ^ (row & 7)) << 2);
            cp_async16(dst, BT + (size_t)(n0 + row) * ldbt + k0 + c * 4, true);
        }
    };

    int T = K >> 5;
    stage(0, 0);
    cp_commit();

    for (int t = 0; t < T; t++) {
        cp_wait0();
        __syncthreads();
        if (t + 1 < T) { stage((t + 1) & 1, (t + 1) * 32); cp_commit(); }

        const float* Ab = As[t & 1];
        const float* Bb = Bs[t & 1];
        #pragma unroll
        for (int kf = 0; kf < 4; kf++) {
            int o0 = (((2 * kf) ^ r) << 2) + cq;
            int o1 = (((2 * kf + 1) ^ r) << 2) + cq;
            unsigned afr[2][4], bfr[4][2];
            #pragma unroll
            for (int mf = 0; mf < 2; mf++) {
                const float* b0 = Ab + (wm + mf * 16 + r) * 32;
                const float* b8 = b0 + 8 * 32;
                if (ACVT) {
                    afr[mf][0] = f2tf(b0[o0]); afr[mf][1] = f2tf(b8[o0]);
                    afr[mf][2] = f2tf(b0[o1]); afr[mf][3] = f2tf(b8[o1]);
                } else {
                    afr[mf][0] = __float_as_uint(b0[o0]); afr[mf][1] = __float_as_uint(b8[o0]);
                    afr[mf][2] = __float_as_uint(b0[o1]); afr[mf][3] = __float_as_uint(b8[o1]);
                }
            }
            #pragma unroll
            for (int nf = 0; nf < 4; nf++) {
                const float* bb = Bb + (wn + nf * 8 + r) * 32;
                bfr[nf][0] = __float_as_uint(bb[o0]);
                bfr[nf][1] = __float_as_uint(bb[o1]);
            }
            #pragma unroll
            for (int mf = 0; mf < 2; mf++)
                #pragma unroll
                for (int nf = 0; nf < 4; nf++)
                    mma_tf32(acc[mf][nf], afr[mf], bfr[nf]);
        }
        __syncthreads();
    }

    #pragma unroll
    for (int mf = 0; mf < 2; mf++) {
        #pragma unroll
        for (int nf = 0; nf < 4; nf++) {
            int col = n0 + wn + nf * 8 + cq * 2;
            float b0 = 0.f, b1 = 0.f;
            if (bias) { b0 = bias[col]; b1 = bias[col + 1]; }
            int row0 = m0 + wm + mf * 16 + r;
            if (row0 < M)
                *(float2*)(C + (size_t)row0 * ldc + col) =
                    make_float2(acc[mf][nf][0] + b0, acc[mf][nf][1] + b1);
            int row1 = row0 + 8;
            if (row1 < M)
                *(float2*)(C + (size_t)row1 * ldc + col) =
                    make_float2(acc[mf][nf][2] + b0, acc[mf][nf][3] + b1);
        }
    }
}

__global__ void gemm1_kernel(const float* __restrict__ inp) {
    __shared__ float As[2][128 * 32];
    __shared__ float Bs[2][64 * 32];
    gemm_body<true>(NN, 256, inp, 256, g_WcatT, 256, g_big, 384, nullptr, As, Bs);
}

__global__ void gemm2_kernel(const float* __restrict__ bias, float* __restrict__ out) {
    __shared__ float As[2][128 * 32];
    __shared__ float Bs[2][64 * 32];
    gemm_body<false>(NN, 128, g_agg, 128, g_WfT, 128, out, 256, bias, As, Bs);
}

// ------------------- edge/attention kernel: one warp per target node -------------------
// Natural [h*32+k] layout; packed slots; ex2 domain. Pass 1 caches the exps of the
// first CACHED edges in SMEM (fp16x4/lane); pass 2 reloads them instead of
// re-gathering as/ap and recomputing -> big issue + L1 savings on ~95% of edges.
__global__ void edge_kernel(const float* __restrict__ edge_w,
                            float* __restrict__ attn) {
    __shared__ uint2 exch[8][CACHED][32];          // 32 KB
    int warp = (blockIdx.x * blockDim.x + threadIdx.x) >> 5;
    int lane = threadIdx.x & 31;
    int wb = (threadIdx.x >> 5) & 7;
    if (warp >= NN) return;
    int n = warp;
    int h = lane >> 3;
    int kb = (lane & 7) * 4;

    float4 at4 = *(const float4*)(g_big + (size_t)n * 384 + 256 + lane * 4);
    float ew0 = edge_w[h * 96 + 64 + kb + 0];
    float ew1 = edge_w[h * 96 + 64 + kb + 1];
    float ew2 = edge_w[h * 96 + 64 + kb + 2];
    float ew3 = edge_w[h * 96 + 64 + kb + 3];
    float den0 = 0.f, den1 = 0.f, den2 = 0.f, den3 = 0.f;
    float acc0 = 0.f, acc1 = 0.f, acc2 = 0.f, acc3 = 0.f;

    int d = g_cnt[n];
    if (d > MAXDEG) d = MAXDEG;
    const int2* sl = g_slot2 + (size_t)n * MAXDEG;
    int2 sa = sl[lane], sb = sl[lane + 32], sc = sl[lane + 64];
    auto get_w0 = [&](int i) {
        int v = (i < 32) ? sa.x : ((i < 64) ? sb.x : sc.x);
        return __shfl_sync(0xffffffffu, v, i & 31);
    };
    auto get_w1 = [&](int i) {
        int v = (i < 32) ? sa.y : ((i < 64) ? sb.y : sc.y);
        return __shfl_sync(0xffffffffu, v, i & 31);
    };

    // pass 1: denominators + cache exps of first CACHED edges in smem
    for (int i = 0; i < d; i++) {
        int w0 = get_w0(i);
        int s = w0 & 0xFFFF;
        int p = ((w0 >> 16) & 0x7F) + 64;
        float4 as4 = *(const float4*)(g_big + (size_t)s * 384 + 128 + lane * 4);
        float4 ap4 = *(const float4*)(g_Apos + p * 128 + lane * 4);
        float x0 = as4.x + at4.x + ap4.x; x0 = fmaxf(x0, 0.2f * x0);
        float x1 = as4.y + at4.y + ap4.y; x1 = fmaxf(x1, 0.2f * x1);
        float x2 = as4.z + at4.z + ap4.z; x2 = fmaxf(x2, 0.2f * x2);
        float x3 = as4.w + at4.w + ap4.w; x3 = fmaxf(x3, 0.2f * x3);
        float e0 = ex2(x0), e1 = ex2(x1), e2 = ex2(x2), e3 = ex2(x3);
        den0 += e0; den1 += e1; den2 += e2; den3 += e3;
        if (i < CACHED) {
            uint2 pk;
            pk.x = pack_h2(e0, e1);
            pk.y = pack_h2(e2, e3);
            exch[wb][i][lane] = pk;
        }
    }
    __syncwarp();

    // fold 1/(den+eps) into beta weights (per-lane)
    ew0 = ew0 / (den0 + 1e-12f);
    ew1 = ew1 / (den1 + 1e-12f);
    ew2 = ew2 / (den2 + 1e-12f);
    ew3 = ew3 / (den3 + 1e-12f);

    // pass 2: cached exps from smem (i < CACHED) else recompute; 8-lane reduction
    for (int i = 0; i < d; i++) {
        int w0 = get_w0(i);
        int e  = get_w1(i);          // warp-uniform shfl, BEFORE any divergence
        int s  = w0 & 0xFFFF;
        int dr = (w0 >> 23) & 0x3F;
        int da = ((unsigned)w0 >> 29) & 0x7;
        float4 vv4 = *(const float4*)(g_big + (size_t)s * 384 + lane * 4);
        float bdr = g_Bdr[dr * 4 + h];
        float bda = g_Bda[da * 4 + h];
        float pl;
        if (i < CACHED) {            // warp-uniform branch
            uint2 pk = exch[wb][i][lane];
            float2 f01 = __half22float2(*(const __half2*)&pk.x);
            float2 f23 = __half22float2(*(const __half2*)&pk.y);
            pl = f01.x * ew0 + f01.y * ew1 + f23.x * ew2 + f23.y * ew3;
        } else {
            int p = ((w0 >> 16) & 0x7F) + 64;
            float4 as4 = *(const float4*)(g_big + (size_t)s * 384 + 128 + lane * 4);
            float4 ap4 = *(const float4*)(g_Apos + p * 128 + lane * 4);
            float x0 = as4.x + at4.x + ap4.x; x0 = fmaxf(x0, 0.2f * x0);
            float x1 = as4.y + at4.y + ap4.y; x1 = fmaxf(x1, 0.2f * x1);
            float x2 = as4.z + at4.z + ap4.z; x2 = fmaxf(x2, 0.2f * x2);
            float x3 = as4.w + at4.w + ap4.w; x3 = fmaxf(x3, 0.2f * x3);
            pl = ex2(x0) * ew0 + ex2(x1) * ew1 + ex2(x2) * ew2 + ex2(x3) * ew3;
        }
        pl += __shfl_xor_sync(0xffffffffu, pl, 1);
        pl += __shfl_xor_sync(0xffffffffu, pl, 2);
        pl += __shfl_xor_sync(0xffffffffu, pl, 4);
        float y = bdr + bda + pl;
        float es = fmaxf(y, 0.2f * y);
        acc0 += vv4.x * es;
        acc1 += vv4.y * es;
        acc2 += vv4.z * es;
        acc3 += vv4.w * es;
        if ((lane & 7) == 0)
            attn[(size_t)e * 4 + h] = es;     // lanes 0/8/16/24 -> one 16B txn
    }

    float4 o = make_float4(f2tff(acc0), f2tff(acc1), f2tff(acc2), f2tff(acc3));
    *(float4*)(g_agg + (size_t)n * 128 + lane * 4) = o;
}

// ------------------- launch -------------------
extern "C" void kernel_launch(void* const* d_in, const int* in_sizes, int n_in,
                              void* d_out, int out_size) {
    const float* inp        = (const float*)d_in[0];
    const int*   relpos     = (const int*)d_in[1];
    // d_in[2] word_rel_pos_edge: unused
    // d_in[3] deprel_ext_edge: unused
    const int*   edge_index = (const int*)d_in[4];
    const int*   deprel     = (const int*)d_in[5];
    const int*   deparc     = (const int*)d_in[6];
    const float* Wkq        = (const float*)d_in[7];
    const float* Wv         = (const float*)d_in[8];
    const float* att_w      = (const float*)d_in[9];
    const float* edge_w     = (const float*)d_in[10];
    const float* Wf         = (const float*)d_in[11];
    const float* final_bias = (const float*)d_in[12];
    const float* E_deprel   = (const float*)d_in[13];
    const float* E_deparc   = (const float*)d_in[14];
    const float* E_pos      = (const float*)d_in[15];

    float* out  = (float*)d_out;             // [N, 256]
    float* attn = out + (size_t)NN * DD;     // [E, 4]

    int prep_n = 384 * 256 + 256 * 128 + 129 * 128 + 256 + 32;   // 147872 > NN
    prep_all_kernel<<<(prep_n + 255) / 256, 256>>>(Wkq, Wv, att_w, Wf,
                                                   E_pos, E_deprel, E_deparc, edge_w);
    scatter_kernel<<<(EE + 255) / 256, 256>>>(edge_index, relpos, deprel, deparc);

    int mt = (NN + 127) / 128;   // 391
    {
        dim3 grid(384 / 64, mt);
        gemm1_kernel<<<grid, 256>>>(inp);
    }

    edge_kernel<<<(NN * 32 + 255) / 256, 256>>>(edge_w, attn);

    {
        dim3 grid(256 / 64, mt);
        gemm2_kernel<<<grid, 256>>>(final_bias, out);
    }
}